// round 2
// baseline (speedup 1.0000x reference)
#include <cuda_runtime.h>

#define NN_D 256          // feature dim D
#define KNEI 16           // neighbors per node

// 50000 * 256 floats = 51.2 MB scratch for the GEMM output ("support")
__device__ float g_support[50000 * 256];

// ---------------------------------------------------------------------------
// GEMM: support[n][o] = sum_d input[n][d] * W[o][d] + b_lin[o]
// A [M, 256] row-major, W [256, 256] row-major (both K-contiguous -> NT gemm)
// 64x64 block tile, 16 k-slice, 256 threads, 4x4 microtile per thread.
// ---------------------------------------------------------------------------
#define BM 64
#define BN 64
#define BK 16

__global__ __launch_bounds__(256) void gemm_kernel(
    const float* __restrict__ A,
    const float* __restrict__ W,
    const float* __restrict__ blin,
    float* __restrict__ C,
    int M)
{
    __shared__ float As[BK][BM];
    __shared__ float Bs[BK][BN];

    const int bm = blockIdx.y * BM;
    const int bn = blockIdx.x * BN;
    const int tid = threadIdx.x;
    const int tx = tid & 15;        // 0..15 -> 4 cols each
    const int ty = tid >> 4;        // 0..15 -> 4 rows each
    const int loadRow  = tid >> 2;        // 0..63
    const int loadQuad = (tid & 3) * 4;   // 0,4,8,12

    float acc[4][4];
#pragma unroll
    for (int i = 0; i < 4; i++)
#pragma unroll
        for (int j = 0; j < 4; j++) acc[i][j] = 0.0f;

    for (int k0 = 0; k0 < NN_D; k0 += BK) {
        // Load A tile (guard rows >= M)
        const int ar = bm + loadRow;
        float4 av;
        if (ar < M) {
            av = *reinterpret_cast<const float4*>(&A[(size_t)ar * NN_D + k0 + loadQuad]);
        } else {
            av = make_float4(0.f, 0.f, 0.f, 0.f);
        }
        As[loadQuad + 0][loadRow] = av.x;
        As[loadQuad + 1][loadRow] = av.y;
        As[loadQuad + 2][loadRow] = av.z;
        As[loadQuad + 3][loadRow] = av.w;

        // Load W tile (N dim is exactly 256, always in-bounds)
        const float4 bv = *reinterpret_cast<const float4*>(
            &W[(size_t)(bn + loadRow) * NN_D + k0 + loadQuad]);
        Bs[loadQuad + 0][loadRow] = bv.x;
        Bs[loadQuad + 1][loadRow] = bv.y;
        Bs[loadQuad + 2][loadRow] = bv.z;
        Bs[loadQuad + 3][loadRow] = bv.w;

        __syncthreads();

#pragma unroll
        for (int kk = 0; kk < BK; kk++) {
            const float4 a = *reinterpret_cast<const float4*>(&As[kk][ty * 4]);
            const float4 b = *reinterpret_cast<const float4*>(&Bs[kk][tx * 4]);
            acc[0][0] += a.x * b.x; acc[0][1] += a.x * b.y;
            acc[0][2] += a.x * b.z; acc[0][3] += a.x * b.w;
            acc[1][0] += a.y * b.x; acc[1][1] += a.y * b.y;
            acc[1][2] += a.y * b.z; acc[1][3] += a.y * b.w;
            acc[2][0] += a.z * b.x; acc[2][1] += a.z * b.y;
            acc[2][2] += a.z * b.z; acc[2][3] += a.z * b.w;
            acc[3][0] += a.w * b.x; acc[3][1] += a.w * b.y;
            acc[3][2] += a.w * b.z; acc[3][3] += a.w * b.w;
        }
        __syncthreads();
    }

    // Epilogue: add b_lin, store
    const float4 bl = *reinterpret_cast<const float4*>(&blin[bn + tx * 4]);
#pragma unroll
    for (int i = 0; i < 4; i++) {
        const int r = bm + ty * 4 + i;
        if (r < M) {
            float4 o;
            o.x = acc[i][0] + bl.x;
            o.y = acc[i][1] + bl.y;
            o.z = acc[i][2] + bl.z;
            o.w = acc[i][3] + bl.w;
            *reinterpret_cast<float4*>(&C[(size_t)r * NN_D + bn + tx * 4]) = o;
        }
    }
}

// ---------------------------------------------------------------------------
// Aggregation: out[n][d] = tanh( sum_k support[a2a[n][k]][d] *
//                                      fedges[node2edge[n][k]][d] ) + bias[d]
// One 64-thread block per node; each thread owns 4 channels (float4).
// NOTE: indices are int32 (JAX demotes int64 without x64 mode).
// ---------------------------------------------------------------------------
__global__ __launch_bounds__(64) void agg_kernel(
    const float* __restrict__ support,
    const float* __restrict__ fedges,
    const int* __restrict__ a2a,
    const int* __restrict__ n2e,
    const float* __restrict__ bias,
    float* __restrict__ out,
    int M)
{
    const int n = blockIdx.x;
    if (n >= M) return;

    __shared__ int sa[KNEI];
    __shared__ int se[KNEI];

    const int t = threadIdx.x;
    if (t < KNEI) {
        sa[t] = a2a[(size_t)n * KNEI + t];
    } else if (t < 2 * KNEI) {
        se[t - KNEI] = n2e[(size_t)n * KNEI + (t - KNEI)];
    }
    __syncthreads();

    const int off = t * 4;
    float4 acc = make_float4(0.f, 0.f, 0.f, 0.f);

#pragma unroll
    for (int k = 0; k < KNEI; k++) {
        const float4 s = *reinterpret_cast<const float4*>(
            &support[(size_t)sa[k] * NN_D + off]);
        const float4 f = *reinterpret_cast<const float4*>(
            &fedges[(size_t)se[k] * NN_D + off]);
        acc.x += s.x * f.x;
        acc.y += s.y * f.y;
        acc.z += s.z * f.z;
        acc.w += s.w * f.w;
    }

    const float4 bl = *reinterpret_cast<const float4*>(&bias[off]);
    float4 o;
    o.x = tanhf(acc.x) + bl.x;
    o.y = tanhf(acc.y) + bl.y;
    o.z = tanhf(acc.z) + bl.z;
    o.w = tanhf(acc.w) + bl.w;
    *reinterpret_cast<float4*>(&out[(size_t)n * NN_D + off]) = o;
}

// ---------------------------------------------------------------------------
// Launch
// ---------------------------------------------------------------------------
extern "C" void kernel_launch(void* const* d_in, const int* in_sizes, int n_in,
                              void* d_out, int out_size)
{
    const float* x    = (const float*)d_in[0];      // input_features [N, D]
    const float* fe   = (const float*)d_in[1];      // fedges [E, D]
    const int*   a2a  = (const int*)d_in[2];        // [N, 16] int32
    const int*   n2e  = (const int*)d_in[3];        // [N, 16] int32
    const float* W    = (const float*)d_in[4];      // [D, D]
    const float* blin = (const float*)d_in[5];      // [D]
    const float* bias = (const float*)d_in[6];      // [D]
    float*       out  = (float*)d_out;              // [N, D]

    const int M = in_sizes[0] / NN_D;               // 50000

    float* sup = nullptr;
    cudaGetSymbolAddress((void**)&sup, g_support);

    dim3 ggrid(NN_D / BN, (M + BM - 1) / BM);       // (4, 782)
    gemm_kernel<<<ggrid, 256>>>(x, W, blin, sup, M);

    agg_kernel<<<M, 64>>>(sup, fe, a2a, n2e, bias, out, M);
}

// round 5
// speedup vs baseline: 1.4466x; 1.4466x over previous
#include <cuda_runtime.h>
#include <cuda_bf16.h>
#include <cstdint>

#define NN_D 256          // feature dim D
#define KNEI 16           // neighbors per node

// 50000 * 256 floats = 51.2 MB scratch for the GEMM output ("support")
__device__ float g_support[50000 * 256];

// ---------------------------------------------------------------------------
// GEMM via mma.sync bf16 hi/lo split (3 MMAs -> ~fp32-ish precision)
// C[M,256] = A[M,256] @ W[256,256]^T + b_lin
// CTA tile 128x128, 8 warps (4M x 2N), warp tile 32x64, K-chunk 64.
// ---------------------------------------------------------------------------
#define BM 128
#define BN 128
#define KC 64
#define LDS 72            // padded bf16 leading dim (72*2=144B rows, conflict-free)

#define AS_H 0
#define AS_L (BM * LDS * 2)            // 18432
#define BS_H (2 * BM * LDS * 2)       // 36864
#define BS_L (3 * BM * LDS * 2)       // 55296
#define SMEM_GEMM (4 * BM * LDS * 2)  // 73728

__device__ __forceinline__ uint32_t smem_u32(const void* p) {
    uint32_t a;
    asm("{ .reg .u64 t; cvta.to.shared.u64 t, %1; cvt.u32.u64 %0, t; }"
        : "=r"(a) : "l"(p));
    return a;
}

__device__ __forceinline__ void cvt_hilo(float x, float y, uint32_t& h, uint32_t& l) {
    __nv_bfloat162 hh, ll;
    hh.x = __float2bfloat16_rn(x);
    hh.y = __float2bfloat16_rn(y);
    ll.x = __float2bfloat16_rn(x - __bfloat162float(hh.x));
    ll.y = __float2bfloat16_rn(y - __bfloat162float(hh.y));
    h = *reinterpret_cast<uint32_t*>(&hh);
    l = *reinterpret_cast<uint32_t*>(&ll);
}

__device__ __forceinline__ void ldm_x4(uint32_t& r0, uint32_t& r1, uint32_t& r2,
                                       uint32_t& r3, uint32_t addr) {
    asm volatile("ldmatrix.sync.aligned.m8n8.x4.shared.b16 {%0,%1,%2,%3}, [%4];"
                 : "=r"(r0), "=r"(r1), "=r"(r2), "=r"(r3) : "r"(addr));
}

__device__ __forceinline__ void mma16816(float* c, const uint32_t* a, const uint32_t* b) {
    asm volatile(
        "mma.sync.aligned.m16n8k16.row.col.f32.bf16.bf16.f32 "
        "{%0,%1,%2,%3}, {%4,%5,%6,%7}, {%8,%9}, {%0,%1,%2,%3};"
        : "+f"(c[0]), "+f"(c[1]), "+f"(c[2]), "+f"(c[3])
        : "r"(a[0]), "r"(a[1]), "r"(a[2]), "r"(a[3]), "r"(b[0]), "r"(b[1]));
}

__global__ __launch_bounds__(256) void gemm_mma_kernel(
    const float* __restrict__ A,
    const float* __restrict__ W,
    const float* __restrict__ blin,
    float* __restrict__ C,
    int M)
{
    extern __shared__ char smem[];
    const uint32_t sbase = smem_u32(smem);
    const int tid  = threadIdx.x;
    const int wid  = tid >> 5;
    const int lane = tid & 31;
    const int warp_m = wid & 3;       // 0..3 -> 32-row slice
    const int warp_n = wid >> 2;      // 0..1 -> 64-col slice
    const int bm = blockIdx.x * BM;
    const int bn = blockIdx.y * BN;

    float acc[2][8][4];
#pragma unroll
    for (int i = 0; i < 2; i++)
#pragma unroll
        for (int j = 0; j < 8; j++)
#pragma unroll
            for (int v = 0; v < 4; v++) acc[i][j][v] = 0.0f;

    // ldmatrix source addresses (per-lane)
    const int a_row = warp_m * 32 + (lane & 15);
    const int a_col = (lane >> 4) * 8;
    const uint32_t a_base = sbase + (uint32_t)(a_row * LDS + a_col) * 2;
    const int b_row_base = warp_n * 64 + ((lane >> 4) << 3) + (lane & 7);
    const int b_col = ((lane >> 3) & 1) * 8;
    const uint32_t b_base = sbase + (uint32_t)(b_row_base * LDS + b_col) * 2;

    for (int c = 0; c < NN_D / KC; c++) {        // 4 K-chunks
        // ---- global -> smem (convert fp32 -> bf16 hi/lo) ----
        // full tile: 128 rows x 64 k = 2048 float4 loads (8 per thread)
#pragma unroll
        for (int i = tid; i < BM * (KC / 4); i += 256) {
            const int row = i >> 4;              // 0..127
            const int q   = i & 15;              // 0..15 -> k offset q*4
            const int gr  = bm + row;
            float4 v = (gr < M)
                ? *reinterpret_cast<const float4*>(A + (size_t)gr * NN_D + c * KC + q * 4)
                : make_float4(0.f, 0.f, 0.f, 0.f);
            uint32_t h0, l0, h1, l1;
            cvt_hilo(v.x, v.y, h0, l0);
            cvt_hilo(v.z, v.w, h1, l1);
            const uint32_t off = (uint32_t)(row * LDS + q * 4) * 2;
            *reinterpret_cast<uint2*>(smem + AS_H + off) = make_uint2(h0, h1);
            *reinterpret_cast<uint2*>(smem + AS_L + off) = make_uint2(l0, l1);

            float4 w = *reinterpret_cast<const float4*>(
                W + (size_t)(bn + row) * NN_D + c * KC + q * 4);
            cvt_hilo(w.x, w.y, h0, l0);
            cvt_hilo(w.z, w.w, h1, l1);
            *reinterpret_cast<uint2*>(smem + BS_H + off) = make_uint2(h0, h1);
            *reinterpret_cast<uint2*>(smem + BS_L + off) = make_uint2(l0, l1);
        }
        __syncthreads();

        // ---- compute: 4 k-steps of 16 ----
#pragma unroll
        for (int ks = 0; ks < KC / 16; ks++) {
            const uint32_t koff = (uint32_t)(ks * 16) * 2;

            uint32_t ah[2][4], al[2][4];
            ldm_x4(ah[0][0], ah[0][1], ah[0][2], ah[0][3], a_base + AS_H + koff);
            ldm_x4(ah[1][0], ah[1][1], ah[1][2], ah[1][3], a_base + AS_H + koff + 16 * LDS * 2);
            ldm_x4(al[0][0], al[0][1], al[0][2], al[0][3], a_base + AS_L + koff);
            ldm_x4(al[1][0], al[1][1], al[1][2], al[1][3], a_base + AS_L + koff + 16 * LDS * 2);

            uint32_t bh[8][2], bl[8][2];
#pragma unroll
            for (int np = 0; np < 4; np++) {
                const uint32_t bo = b_base + koff + (uint32_t)(np * 16 * LDS) * 2;
                ldm_x4(bh[2 * np][0], bh[2 * np][1], bh[2 * np + 1][0], bh[2 * np + 1][1],
                       bo + BS_H);
                ldm_x4(bl[2 * np][0], bl[2 * np][1], bl[2 * np + 1][0], bl[2 * np + 1][1],
                       bo + BS_L);
            }

#pragma unroll
            for (int mi = 0; mi < 2; mi++) {
#pragma unroll
                for (int nj = 0; nj < 8; nj++) {
                    mma16816(acc[mi][nj], ah[mi], bh[nj]);
                    mma16816(acc[mi][nj], ah[mi], bl[nj]);
                    mma16816(acc[mi][nj], al[mi], bh[nj]);
                }
            }
        }
        __syncthreads();
    }

    // ---- epilogue: + b_lin, store ----
    float2 blv[8];
#pragma unroll
    for (int nj = 0; nj < 8; nj++) {
        const int col = bn + warp_n * 64 + nj * 8 + (lane & 3) * 2;
        blv[nj].x = __ldg(blin + col);
        blv[nj].y = __ldg(blin + col + 1);
    }
#pragma unroll
    for (int mi = 0; mi < 2; mi++) {
        const int r0 = bm + warp_m * 32 + mi * 16 + (lane >> 2);
        const int r1 = r0 + 8;
#pragma unroll
        for (int nj = 0; nj < 8; nj++) {
            const int col = bn + warp_n * 64 + nj * 8 + (lane & 3) * 2;
            if (r0 < M) {
                float2 o = make_float2(acc[mi][nj][0] + blv[nj].x,
                                       acc[mi][nj][1] + blv[nj].y);
                *reinterpret_cast<float2*>(C + (size_t)r0 * NN_D + col) = o;
            }
            if (r1 < M) {
                float2 o = make_float2(acc[mi][nj][2] + blv[nj].x,
                                       acc[mi][nj][3] + blv[nj].y);
                *reinterpret_cast<float2*>(C + (size_t)r1 * NN_D + col) = o;
            }
        }
    }
}

// ---------------------------------------------------------------------------
// Aggregation: out[n][d] = tanh(sum_k sup[a2a[n][k]][d] * fe[n2e[n][k]][d]) + bias[d]
// ---------------------------------------------------------------------------
__global__ __launch_bounds__(64) void agg_kernel(
    const float* __restrict__ support,
    const float* __restrict__ fedges,
    const int* __restrict__ a2a,
    const int* __restrict__ n2e,
    const float* __restrict__ bias,
    float* __restrict__ out,
    int M)
{
    const int n = blockIdx.x;
    if (n >= M) return;

    __shared__ int sa[KNEI];
    __shared__ int se[KNEI];

    const int t = threadIdx.x;
    if (t < KNEI) {
        sa[t] = a2a[(size_t)n * KNEI + t];
    } else if (t < 2 * KNEI) {
        se[t - KNEI] = n2e[(size_t)n * KNEI + (t - KNEI)];
    }
    __syncthreads();

    const int off = t * 4;
    float4 acc = make_float4(0.f, 0.f, 0.f, 0.f);

#pragma unroll
    for (int k = 0; k < KNEI; k++) {
        const float4 s = *reinterpret_cast<const float4*>(&support[(size_t)sa[k] * NN_D + off]);
        const float4 f = *reinterpret_cast<const float4*>(&fedges[(size_t)se[k] * NN_D + off]);
        acc.x += s.x * f.x;
        acc.y += s.y * f.y;
        acc.z += s.z * f.z;
        acc.w += s.w * f.w;
    }

    const float4 bl = *reinterpret_cast<const float4*>(&bias[off]);
    float4 o;
    o.x = tanhf(acc.x) + bl.x;
    o.y = tanhf(acc.y) + bl.y;
    o.z = tanhf(acc.z) + bl.z;
    o.w = tanhf(acc.w) + bl.w;
    *reinterpret_cast<float4*>(&out[(size_t)n * NN_D + off]) = o;
}

// ---------------------------------------------------------------------------
// Launch
// ---------------------------------------------------------------------------
extern "C" void kernel_launch(void* const* d_in, const int* in_sizes, int n_in,
                              void* d_out, int out_size)
{
    const float* x    = (const float*)d_in[0];
    const float* fe   = (const float*)d_in[1];
    const int*   a2a  = (const int*)d_in[2];
    const int*   n2e  = (const int*)d_in[3];
    const float* W    = (const float*)d_in[4];
    const float* blin = (const float*)d_in[5];
    const float* bias = (const float*)d_in[6];
    float*       out  = (float*)d_out;

    const int M = in_sizes[0] / NN_D;               // 50000

    float* sup = nullptr;
    cudaGetSymbolAddress((void**)&sup, g_support);

    cudaFuncSetAttribute(gemm_mma_kernel,
                         cudaFuncAttributeMaxDynamicSharedMemorySize, SMEM_GEMM);

    dim3 ggrid((M + BM - 1) / BM, NN_D / BN);       // (391, 2)
    gemm_mma_kernel<<<ggrid, 256, SMEM_GEMM>>>(x, W, blin, sup, M);

    agg_kernel<<<M, 64>>>(sup, fe, a2a, n2e, bias, out, M);
}

// round 6
// speedup vs baseline: 1.6124x; 1.1146x over previous
#include <cuda_runtime.h>
#include <cuda_bf16.h>
#include <cstdint>

#define NN_D 256          // feature dim D
#define KNEI 16           // neighbors per node

// 50000 * 256 floats = 51.2 MB scratch for the GEMM output ("support")
__device__ float g_support[50000 * 256];

// ---------------------------------------------------------------------------
// GEMM via mma.sync bf16 hi/lo split (3 MMAs -> ~fp32-ish precision)
// C[M,256] = A[M,256] @ W[256,256]^T + b_lin
// CTA tile 128x128, 8 warps (4M x 2N), warp tile 32x64, K-chunk 64.
// ---------------------------------------------------------------------------
#define BM 128
#define BN 128
#define KC 64
#define LDS 72            // padded bf16 leading dim (72*2=144B rows, conflict-free)

#define AS_H 0
#define AS_L (BM * LDS * 2)            // 18432
#define BS_H (2 * BM * LDS * 2)       // 36864
#define BS_L (3 * BM * LDS * 2)       // 55296
#define SMEM_GEMM (4 * BM * LDS * 2)  // 73728

__device__ __forceinline__ uint32_t smem_u32(const void* p) {
    uint32_t a;
    asm("{ .reg .u64 t; cvta.to.shared.u64 t, %1; cvt.u32.u64 %0, t; }"
        : "=r"(a) : "l"(p));
    return a;
}

__device__ __forceinline__ void cvt_hilo(float x, float y, uint32_t& h, uint32_t& l) {
    __nv_bfloat162 hh, ll;
    hh.x = __float2bfloat16_rn(x);
    hh.y = __float2bfloat16_rn(y);
    ll.x = __float2bfloat16_rn(x - __bfloat162float(hh.x));
    ll.y = __float2bfloat16_rn(y - __bfloat162float(hh.y));
    h = *reinterpret_cast<uint32_t*>(&hh);
    l = *reinterpret_cast<uint32_t*>(&ll);
}

__device__ __forceinline__ void ldm_x4(uint32_t& r0, uint32_t& r1, uint32_t& r2,
                                       uint32_t& r3, uint32_t addr) {
    asm volatile("ldmatrix.sync.aligned.m8n8.x4.shared.b16 {%0,%1,%2,%3}, [%4];"
                 : "=r"(r0), "=r"(r1), "=r"(r2), "=r"(r3) : "r"(addr));
}

__device__ __forceinline__ void mma16816(float* c, const uint32_t* a, const uint32_t* b) {
    asm volatile(
        "mma.sync.aligned.m16n8k16.row.col.f32.bf16.bf16.f32 "
        "{%0,%1,%2,%3}, {%4,%5,%6,%7}, {%8,%9}, {%0,%1,%2,%3};"
        : "+f"(c[0]), "+f"(c[1]), "+f"(c[2]), "+f"(c[3])
        : "r"(a[0]), "r"(a[1]), "r"(a[2]), "r"(a[3]), "r"(b[0]), "r"(b[1]));
}

__global__ __launch_bounds__(256) void gemm_mma_kernel(
    const float* __restrict__ A,
    const float* __restrict__ W,
    const float* __restrict__ blin,
    float* __restrict__ C,
    int M)
{
    extern __shared__ char smem[];
    const uint32_t sbase = smem_u32(smem);
    const int tid  = threadIdx.x;
    const int wid  = tid >> 5;
    const int lane = tid & 31;
    const int warp_m = wid & 3;       // 0..3 -> 32-row slice
    const int warp_n = wid >> 2;      // 0..1 -> 64-col slice
    const int bm = blockIdx.x * BM;
    const int bn = blockIdx.y * BN;

    float acc[2][8][4];
#pragma unroll
    for (int i = 0; i < 2; i++)
#pragma unroll
        for (int j = 0; j < 8; j++)
#pragma unroll
            for (int v = 0; v < 4; v++) acc[i][j][v] = 0.0f;

    // ldmatrix source addresses (per-lane)
    const int a_row = warp_m * 32 + (lane & 15);
    const int a_col = (lane >> 4) * 8;
    const uint32_t a_base = sbase + (uint32_t)(a_row * LDS + a_col) * 2;
    const int b_row_base = warp_n * 64 + ((lane >> 4) << 3) + (lane & 7);
    const int b_col = ((lane >> 3) & 1) * 8;
    const uint32_t b_base = sbase + (uint32_t)(b_row_base * LDS + b_col) * 2;

    for (int c = 0; c < NN_D / KC; c++) {        // 4 K-chunks
        // ---- global -> smem (convert fp32 -> bf16 hi/lo) ----
        // full tile: 128 rows x 64 k = 2048 float4 loads (8 per thread)
#pragma unroll
        for (int i = tid; i < BM * (KC / 4); i += 256) {
            const int row = i >> 4;              // 0..127
            const int q   = i & 15;              // 0..15 -> k offset q*4
            const int gr  = bm + row;
            float4 v = (gr < M)
                ? *reinterpret_cast<const float4*>(A + (size_t)gr * NN_D + c * KC + q * 4)
                : make_float4(0.f, 0.f, 0.f, 0.f);
            uint32_t h0, l0, h1, l1;
            cvt_hilo(v.x, v.y, h0, l0);
            cvt_hilo(v.z, v.w, h1, l1);
            const uint32_t off = (uint32_t)(row * LDS + q * 4) * 2;
            *reinterpret_cast<uint2*>(smem + AS_H + off) = make_uint2(h0, h1);
            *reinterpret_cast<uint2*>(smem + AS_L + off) = make_uint2(l0, l1);

            float4 w = *reinterpret_cast<const float4*>(
                W + (size_t)(bn + row) * NN_D + c * KC + q * 4);
            cvt_hilo(w.x, w.y, h0, l0);
            cvt_hilo(w.z, w.w, h1, l1);
            *reinterpret_cast<uint2*>(smem + BS_H + off) = make_uint2(h0, h1);
            *reinterpret_cast<uint2*>(smem + BS_L + off) = make_uint2(l0, l1);
        }
        __syncthreads();

        // ---- compute: 4 k-steps of 16 ----
#pragma unroll
        for (int ks = 0; ks < KC / 16; ks++) {
            const uint32_t koff = (uint32_t)(ks * 16) * 2;

            uint32_t ah[2][4], al[2][4];
            ldm_x4(ah[0][0], ah[0][1], ah[0][2], ah[0][3], a_base + AS_H + koff);
            ldm_x4(ah[1][0], ah[1][1], ah[1][2], ah[1][3], a_base + AS_H + koff + 16 * LDS * 2);
            ldm_x4(al[0][0], al[0][1], al[0][2], al[0][3], a_base + AS_L + koff);
            ldm_x4(al[1][0], al[1][1], al[1][2], al[1][3], a_base + AS_L + koff + 16 * LDS * 2);

            uint32_t bh[8][2], bl[8][2];
#pragma unroll
            for (int np = 0; np < 4; np++) {
                const uint32_t bo = b_base + koff + (uint32_t)(np * 16 * LDS) * 2;
                ldm_x4(bh[2 * np][0], bh[2 * np][1], bh[2 * np + 1][0], bh[2 * np + 1][1],
                       bo + BS_H);
                ldm_x4(bl[2 * np][0], bl[2 * np][1], bl[2 * np + 1][0], bl[2 * np + 1][1],
                       bo + BS_L);
            }

#pragma unroll
            for (int mi = 0; mi < 2; mi++) {
#pragma unroll
                for (int nj = 0; nj < 8; nj++) {
                    mma16816(acc[mi][nj], ah[mi], bh[nj]);
                    mma16816(acc[mi][nj], ah[mi], bl[nj]);
                    mma16816(acc[mi][nj], al[mi], bh[nj]);
                }
            }
        }
        __syncthreads();
    }

    // ---- epilogue: + b_lin, store ----
    float2 blv[8];
#pragma unroll
    for (int nj = 0; nj < 8; nj++) {
        const int col = bn + warp_n * 64 + nj * 8 + (lane & 3) * 2;
        blv[nj].x = __ldg(blin + col);
        blv[nj].y = __ldg(blin + col + 1);
    }
#pragma unroll
    for (int mi = 0; mi < 2; mi++) {
        const int r0 = bm + warp_m * 32 + mi * 16 + (lane >> 2);
        const int r1 = r0 + 8;
#pragma unroll
        for (int nj = 0; nj < 8; nj++) {
            const int col = bn + warp_n * 64 + nj * 8 + (lane & 3) * 2;
            if (r0 < M) {
                float2 o = make_float2(acc[mi][nj][0] + blv[nj].x,
                                       acc[mi][nj][1] + blv[nj].y);
                *reinterpret_cast<float2*>(C + (size_t)r0 * NN_D + col) = o;
            }
            if (r1 < M) {
                float2 o = make_float2(acc[mi][nj][2] + blv[nj].x,
                                       acc[mi][nj][3] + blv[nj].y);
                *reinterpret_cast<float2*>(C + (size_t)r1 * NN_D + col) = o;
            }
        }
    }
}

// ---------------------------------------------------------------------------
// Aggregation: out[n][d] = tanh(sum_k sup[a2a[n][k]][d] * fe[n2e[n][k]][d]) + bias[d]
// fedges has ~zero reuse -> load evict-first (__ldcs) so the 51 MB support
// table stays L2-resident. Output stores likewise streamed (__stcs).
// ---------------------------------------------------------------------------
__global__ __launch_bounds__(64) void agg_kernel(
    const float* __restrict__ support,
    const float* __restrict__ fedges,
    const int* __restrict__ a2a,
    const int* __restrict__ n2e,
    const float* __restrict__ bias,
    float* __restrict__ out,
    int M)
{
    const int n = blockIdx.x;
    if (n >= M) return;

    __shared__ int sa[KNEI];
    __shared__ int se[KNEI];

    const int t = threadIdx.x;
    if (t < KNEI) {
        sa[t] = a2a[(size_t)n * KNEI + t];
    } else if (t < 2 * KNEI) {
        se[t - KNEI] = n2e[(size_t)n * KNEI + (t - KNEI)];
    }
    __syncthreads();

    const int off = t * 4;
    float4 acc = make_float4(0.f, 0.f, 0.f, 0.f);

#pragma unroll
    for (int k = 0; k < KNEI; k++) {
        const float4 s = *reinterpret_cast<const float4*>(&support[(size_t)sa[k] * NN_D + off]);
        const float4 f = __ldcs(reinterpret_cast<const float4*>(
            &fedges[(size_t)se[k] * NN_D + off]));
        acc.x += s.x * f.x;
        acc.y += s.y * f.y;
        acc.z += s.z * f.z;
        acc.w += s.w * f.w;
    }

    const float4 bl = *reinterpret_cast<const float4*>(&bias[off]);
    float4 o;
    o.x = tanhf(acc.x) + bl.x;
    o.y = tanhf(acc.y) + bl.y;
    o.z = tanhf(acc.z) + bl.z;
    o.w = tanhf(acc.w) + bl.w;
    __stcs(reinterpret_cast<float4*>(&out[(size_t)n * NN_D + off]), o);
}

// ---------------------------------------------------------------------------
// Launch
// ---------------------------------------------------------------------------
extern "C" void kernel_launch(void* const* d_in, const int* in_sizes, int n_in,
                              void* d_out, int out_size)
{
    const float* x    = (const float*)d_in[0];
    const float* fe   = (const float*)d_in[1];
    const int*   a2a  = (const int*)d_in[2];
    const int*   n2e  = (const int*)d_in[3];
    const float* W    = (const float*)d_in[4];
    const float* blin = (const float*)d_in[5];
    const float* bias = (const float*)d_in[6];
    float*       out  = (float*)d_out;

    const int M = in_sizes[0] / NN_D;               // 50000

    float* sup = nullptr;
    cudaGetSymbolAddress((void**)&sup, g_support);

    cudaFuncSetAttribute(gemm_mma_kernel,
                         cudaFuncAttributeMaxDynamicSharedMemorySize, SMEM_GEMM);

    dim3 ggrid((M + BM - 1) / BM, NN_D / BN);       // (391, 2)
    gemm_mma_kernel<<<ggrid, 256, SMEM_GEMM>>>(x, W, blin, sup, M);

    agg_kernel<<<M, 64>>>(sup, fe, a2a, n2e, bias, out, M);
}

// round 7
// speedup vs baseline: 1.9315x; 1.1979x over previous
#include <cuda_runtime.h>
#include <cuda_fp16.h>
#include <cstdint>

#define NN_D 256          // feature dim D
#define KNEI 16           // neighbors per node

// 50000 * 256 floats = 51.2 MB scratch for the GEMM output ("support")
__device__ float g_support[50000 * 256];

// ---------------------------------------------------------------------------
// GEMM via mma.sync fp16: A split hi/lo (e5m10 -> ~22 mantissa bits), B single
// fp16 (eps 2^-11). 2 MMAs per fragment pair: D = Ah*B + Al*B.
// C[M,256] = A[M,256] @ W[256,256]^T + b_lin
// CTA tile 128x128, 8 warps (4M x 2N), warp tile 32x64, K-chunk 64.
// ---------------------------------------------------------------------------
#define BM 128
#define BN 128
#define KC 64
#define LDS 72            // padded fp16 leading dim (conflict-free ldmatrix)

#define AS_H 0
#define AS_L (BM * LDS * 2)            // 18432
#define BS   (2 * BM * LDS * 2)       // 36864
#define SMEM_GEMM (3 * BM * LDS * 2)  // 55296

__device__ __forceinline__ uint32_t smem_u32(const void* p) {
    uint32_t a;
    asm("{ .reg .u64 t; cvta.to.shared.u64 t, %1; cvt.u32.u64 %0, t; }"
        : "=r"(a) : "l"(p));
    return a;
}

// fp16 hi/lo split of a float pair
__device__ __forceinline__ void cvt_hilo_f16(float x, float y, uint32_t& h, uint32_t& l) {
    __half2 hh, ll;
    hh.x = __float2half_rn(x);
    hh.y = __float2half_rn(y);
    ll.x = __float2half_rn(x - __half2float(hh.x));
    ll.y = __float2half_rn(y - __half2float(hh.y));
    h = *reinterpret_cast<uint32_t*>(&hh);
    l = *reinterpret_cast<uint32_t*>(&ll);
}

__device__ __forceinline__ uint32_t cvt_f16x2(float x, float y) {
    __half2 hh;
    hh.x = __float2half_rn(x);
    hh.y = __float2half_rn(y);
    return *reinterpret_cast<uint32_t*>(&hh);
}

__device__ __forceinline__ void ldm_x4(uint32_t& r0, uint32_t& r1, uint32_t& r2,
                                       uint32_t& r3, uint32_t addr) {
    asm volatile("ldmatrix.sync.aligned.m8n8.x4.shared.b16 {%0,%1,%2,%3}, [%4];"
                 : "=r"(r0), "=r"(r1), "=r"(r2), "=r"(r3) : "r"(addr));
}

__device__ __forceinline__ void mma16816(float* c, const uint32_t* a, const uint32_t* b) {
    asm volatile(
        "mma.sync.aligned.m16n8k16.row.col.f32.f16.f16.f32 "
        "{%0,%1,%2,%3}, {%4,%5,%6,%7}, {%8,%9}, {%0,%1,%2,%3};"
        : "+f"(c[0]), "+f"(c[1]), "+f"(c[2]), "+f"(c[3])
        : "r"(a[0]), "r"(a[1]), "r"(a[2]), "r"(a[3]), "r"(b[0]), "r"(b[1]));
}

__global__ __launch_bounds__(256) void gemm_mma_kernel(
    const float* __restrict__ A,
    const float* __restrict__ W,
    const float* __restrict__ blin,
    float* __restrict__ C,
    int M)
{
    extern __shared__ char smem[];
    const uint32_t sbase = smem_u32(smem);
    const int tid  = threadIdx.x;
    const int wid  = tid >> 5;
    const int lane = tid & 31;
    const int warp_m = wid & 3;       // 0..3 -> 32-row slice
    const int warp_n = wid >> 2;      // 0..1 -> 64-col slice
    const int bm = blockIdx.x * BM;
    const int bn = blockIdx.y * BN;

    float acc[2][8][4];
#pragma unroll
    for (int i = 0; i < 2; i++)
#pragma unroll
        for (int j = 0; j < 8; j++)
#pragma unroll
            for (int v = 0; v < 4; v++) acc[i][j][v] = 0.0f;

    // ldmatrix source addresses (per-lane)
    const int a_row = warp_m * 32 + (lane & 15);
    const int a_col = (lane >> 4) * 8;
    const uint32_t a_base = sbase + (uint32_t)(a_row * LDS + a_col) * 2;
    const int b_row_base = warp_n * 64 + ((lane >> 4) << 3) + (lane & 7);
    const int b_col = ((lane >> 3) & 1) * 8;
    const uint32_t b_base = sbase + (uint32_t)(b_row_base * LDS + b_col) * 2;

    for (int c = 0; c < NN_D / KC; c++) {        // 4 K-chunks
        // ---- global -> smem (convert fp32 -> fp16 hi/lo for A, fp16 for B) ----
        // full tile: 128 rows x 64 k = 2048 float4 loads (8 per thread)
#pragma unroll
        for (int i = tid; i < BM * (KC / 4); i += 256) {
            const int row = i >> 4;              // 0..127
            const int q   = i & 15;              // 0..15 -> k offset q*4
            const int gr  = bm + row;
            float4 v = (gr < M)
                ? *reinterpret_cast<const float4*>(A + (size_t)gr * NN_D + c * KC + q * 4)
                : make_float4(0.f, 0.f, 0.f, 0.f);
            uint32_t h0, l0, h1, l1;
            cvt_hilo_f16(v.x, v.y, h0, l0);
            cvt_hilo_f16(v.z, v.w, h1, l1);
            const uint32_t off = (uint32_t)(row * LDS + q * 4) * 2;
            *reinterpret_cast<uint2*>(smem + AS_H + off) = make_uint2(h0, h1);
            *reinterpret_cast<uint2*>(smem + AS_L + off) = make_uint2(l0, l1);

            float4 w = *reinterpret_cast<const float4*>(
                W + (size_t)(bn + row) * NN_D + c * KC + q * 4);
            *reinterpret_cast<uint2*>(smem + BS + off) =
                make_uint2(cvt_f16x2(w.x, w.y), cvt_f16x2(w.z, w.w));
        }
        __syncthreads();

        // ---- compute: 4 k-steps of 16 ----
#pragma unroll
        for (int ks = 0; ks < KC / 16; ks++) {
            const uint32_t koff = (uint32_t)(ks * 16) * 2;

            uint32_t ah[2][4], al[2][4];
            ldm_x4(ah[0][0], ah[0][1], ah[0][2], ah[0][3], a_base + AS_H + koff);
            ldm_x4(ah[1][0], ah[1][1], ah[1][2], ah[1][3], a_base + AS_H + koff + 16 * LDS * 2);
            ldm_x4(al[0][0], al[0][1], al[0][2], al[0][3], a_base + AS_L + koff);
            ldm_x4(al[1][0], al[1][1], al[1][2], al[1][3], a_base + AS_L + koff + 16 * LDS * 2);

            uint32_t bf[8][2];
#pragma unroll
            for (int np = 0; np < 4; np++) {
                const uint32_t bo = b_base + koff + (uint32_t)(np * 16 * LDS) * 2;
                ldm_x4(bf[2 * np][0], bf[2 * np][1], bf[2 * np + 1][0], bf[2 * np + 1][1],
                       bo + BS);
            }

#pragma unroll
            for (int mi = 0; mi < 2; mi++) {
#pragma unroll
                for (int nj = 0; nj < 8; nj++) {
                    mma16816(acc[mi][nj], ah[mi], bf[nj]);
                    mma16816(acc[mi][nj], al[mi], bf[nj]);
                }
            }
        }
        __syncthreads();
    }

    // ---- epilogue: + b_lin, store ----
    float2 blv[8];
#pragma unroll
    for (int nj = 0; nj < 8; nj++) {
        const int col = bn + warp_n * 64 + nj * 8 + (lane & 3) * 2;
        blv[nj].x = __ldg(blin + col);
        blv[nj].y = __ldg(blin + col + 1);
    }
#pragma unroll
    for (int mi = 0; mi < 2; mi++) {
        const int r0 = bm + warp_m * 32 + mi * 16 + (lane >> 2);
        const int r1 = r0 + 8;
#pragma unroll
        for (int nj = 0; nj < 8; nj++) {
            const int col = bn + warp_n * 64 + nj * 8 + (lane & 3) * 2;
            if (r0 < M) {
                float2 o = make_float2(acc[mi][nj][0] + blv[nj].x,
                                       acc[mi][nj][1] + blv[nj].y);
                *reinterpret_cast<float2*>(C + (size_t)r0 * NN_D + col) = o;
            }
            if (r1 < M) {
                float2 o = make_float2(acc[mi][nj][2] + blv[nj].x,
                                       acc[mi][nj][3] + blv[nj].y);
                *reinterpret_cast<float2*>(C + (size_t)r1 * NN_D + col) = o;
            }
        }
    }
}

// ---------------------------------------------------------------------------
// Aggregation: out[n][d] = tanh(sum_k sup[a2a[n][k]][d] * fe[n2e[n][k]][d]) + bias[d]
// fedges has ~zero reuse -> load evict-first (__ldcs) so the 51 MB support
// table stays L2-resident. Output stores likewise streamed (__stcs).
// ---------------------------------------------------------------------------
__global__ __launch_bounds__(64) void agg_kernel(
    const float* __restrict__ support,
    const float* __restrict__ fedges,
    const int* __restrict__ a2a,
    const int* __restrict__ n2e,
    const float* __restrict__ bias,
    float* __restrict__ out,
    int M)
{
    const int n = blockIdx.x;
    if (n >= M) return;

    __shared__ int sa[KNEI];
    __shared__ int se[KNEI];

    const int t = threadIdx.x;
    if (t < KNEI) {
        sa[t] = a2a[(size_t)n * KNEI + t];
    } else if (t < 2 * KNEI) {
        se[t - KNEI] = n2e[(size_t)n * KNEI + (t - KNEI)];
    }
    __syncthreads();

    const int off = t * 4;
    float4 acc = make_float4(0.f, 0.f, 0.f, 0.f);

#pragma unroll
    for (int k = 0; k < KNEI; k++) {
        const float4 s = *reinterpret_cast<const float4*>(&support[(size_t)sa[k] * NN_D + off]);
        const float4 f = __ldcs(reinterpret_cast<const float4*>(
            &fedges[(size_t)se[k] * NN_D + off]));
        acc.x += s.x * f.x;
        acc.y += s.y * f.y;
        acc.z += s.z * f.z;
        acc.w += s.w * f.w;
    }

    const float4 bl = *reinterpret_cast<const float4*>(&bias[off]);
    float4 o;
    o.x = tanhf(acc.x) + bl.x;
    o.y = tanhf(acc.y) + bl.y;
    o.z = tanhf(acc.z) + bl.z;
    o.w = tanhf(acc.w) + bl.w;
    __stcs(reinterpret_cast<float4*>(&out[(size_t)n * NN_D + off]), o);
}

// ---------------------------------------------------------------------------
// Launch
// ---------------------------------------------------------------------------
extern "C" void kernel_launch(void* const* d_in, const int* in_sizes, int n_in,
                              void* d_out, int out_size)
{
    const float* x    = (const float*)d_in[0];
    const float* fe   = (const float*)d_in[1];
    const int*   a2a  = (const int*)d_in[2];
    const int*   n2e  = (const int*)d_in[3];
    const float* W    = (const float*)d_in[4];
    const float* blin = (const float*)d_in[5];
    const float* bias = (const float*)d_in[6];
    float*       out  = (float*)d_out;

    const int M = in_sizes[0] / NN_D;               // 50000

    float* sup = nullptr;
    cudaGetSymbolAddress((void**)&sup, g_support);

    cudaFuncSetAttribute(gemm_mma_kernel,
                         cudaFuncAttributeMaxDynamicSharedMemorySize, SMEM_GEMM);

    dim3 ggrid((M + BM - 1) / BM, NN_D / BN);       // (391, 2)
    gemm_mma_kernel<<<ggrid, 256, SMEM_GEMM>>>(x, W, blin, sup, M);

    agg_kernel<<<M, 64>>>(sup, fe, a2a, n2e, bias, out, M);
}